// round 1
// baseline (speedup 1.0000x reference)
#include <cuda_runtime.h>

// Problem dims (fixed by the dataset)
#define BDIM 64
#define NDIM 512
#define HDIM 2048
#define HP   (HDIM / 2)   // packed h-pairs

// ---------------------------------------------------------------------------
// Device scratch (allocation-free rule: __device__ globals)
// ---------------------------------------------------------------------------
__device__ ulonglong2 g_CS[NDIM * HP];       // [k][hp]: .x = packed (C0,C1), .y = packed (S0,S1); C=cosh(2W), S=sinh(2W)
__device__ float      g_T[2 * BDIM * HDIM];  // [sgnSel][b][h]: sel0 = -tanh(z), sel1 = +tanh(z)
__device__ float      g_xT[NDIM * BDIM];     // x transposed: [n][b]
__device__ float      g_P[BDIM * NDIM];      // per-(b,k) product of cosh ratios

// ---------------------------------------------------------------------------
// f32x2 packed helpers (Blackwell packed fp32 pipes)
// ---------------------------------------------------------------------------
__device__ __forceinline__ unsigned long long pk2(float lo, float hi) {
    unsigned long long r;
    asm("mov.b64 %0, {%1, %2};" : "=l"(r) : "f"(lo), "f"(hi));
    return r;
}
__device__ __forceinline__ unsigned long long fma2(unsigned long long a, unsigned long long b, unsigned long long c) {
    unsigned long long r;
    asm("fma.rn.f32x2 %0, %1, %2, %3;" : "=l"(r) : "l"(a), "l"(b), "l"(c));
    return r;
}
__device__ __forceinline__ unsigned long long mul2(unsigned long long a, unsigned long long b) {
    unsigned long long r;
    asm("mul.rn.f32x2 %0, %1, %2;" : "=l"(r) : "l"(a), "l"(b));
    return r;
}
__device__ __forceinline__ float2 up2(unsigned long long p) {
    float lo, hi;
    asm("mov.b64 {%0, %1}, %2;" : "=f"(lo), "=f"(hi) : "l"(p));
    return make_float2(lo, hi);
}

// ---------------------------------------------------------------------------
// Kernel 1: precompute C = cosh(2W), S = sinh(2W), packed per h-pair
// ---------------------------------------------------------------------------
__global__ void prep_cs_kernel(const float* __restrict__ W) {
    int idx = blockIdx.x * blockDim.x + threadIdx.x;   // over NDIM*HP
    if (idx >= NDIM * HP) return;
    // element addr: k*HDIM + 2*hp == 2*idx
    float2 w = *reinterpret_cast<const float2*>(W + 2 * idx);
    float c0 = coshf(2.0f * w.x), s0 = sinhf(2.0f * w.x);
    float c1 = coshf(2.0f * w.y), s1 = sinhf(2.0f * w.y);
    g_CS[idx] = make_ulonglong2(pk2(c0, c1), pk2(s0, s1));
}

// ---------------------------------------------------------------------------
// Kernel 2: transpose x -> xT[n][b]  (for vectorized z-GEMM)
// ---------------------------------------------------------------------------
__global__ void xpose_kernel(const float* __restrict__ x) {
    int idx = blockIdx.x * blockDim.x + threadIdx.x;
    if (idx < BDIM * NDIM) {
        int b = idx / NDIM, n = idx % NDIM;
        g_xT[n * BDIM + b] = x[idx];
    }
}

// ---------------------------------------------------------------------------
// Kernel 3: z = x@W + bias, T = tanh(z), store both +/- sign rows.
// Thread owns (h, 4 consecutive b) -> 4 accumulators, W read once per 4 b.
// grid (HDIM/256, BDIM/4), block 256
// ---------------------------------------------------------------------------
__global__ void __launch_bounds__(256) z_tanh_kernel(const float* __restrict__ W,
                                                     const float* __restrict__ bias) {
    int h  = blockIdx.x * 256 + threadIdx.x;
    int b0 = blockIdx.y * 4;
    float bv = bias[h];
    float z0 = bv, z1 = bv, z2 = bv, z3 = bv;
    const float*  wp = W + h;
    const float4* xp = reinterpret_cast<const float4*>(g_xT) + (b0 >> 2);
#pragma unroll 4
    for (int n = 0; n < NDIM; n++) {
        float  w  = wp[n * HDIM];              // coalesced across threads
        float4 xv = xp[n * (BDIM / 4)];        // block-uniform (broadcast)
        z0 = fmaf(xv.x, w, z0);
        z1 = fmaf(xv.y, w, z1);
        z2 = fmaf(xv.z, w, z2);
        z3 = fmaf(xv.w, w, z3);
    }
    float t0 = tanhf(z0), t1 = tanhf(z1), t2 = tanhf(z2), t3 = tanhf(z3);
    float* Tm = g_T;                 // sel 0: -tanh (used when x_k = +1)
    float* Tp = g_T + BDIM * HDIM;   // sel 1: +tanh (used when x_k = -1)
    Tm[(b0 + 0) * HDIM + h] = -t0;   Tp[(b0 + 0) * HDIM + h] = t0;
    Tm[(b0 + 1) * HDIM + h] = -t1;   Tp[(b0 + 1) * HDIM + h] = t1;
    Tm[(b0 + 2) * HDIM + h] = -t2;   Tp[(b0 + 2) * HDIM + h] = t2;
    Tm[(b0 + 3) * HDIM + h] = -t3;   Tp[(b0 + 3) * HDIM + h] = t3;
}

// ---------------------------------------------------------------------------
// Kernel 4: main product kernel.
//   P[b,k] = prod_h ( C[k,h] - x[b,k] * tanh(z[b,h]) * S[k,h] )
// Block = 8 warps = 8 b's; block loops 16 k's in lockstep so all 8 warps
// pull the same 16KB CS row (L1 merge) and each warp's T rows stay L1-hot.
// grid (NDIM/16, BDIM/8), block 256
// ---------------------------------------------------------------------------
__global__ void __launch_bounds__(256) prod_kernel(const float* __restrict__ x) {
    int lane = threadIdx.x & 31;
    int warp = threadIdx.x >> 5;
    int b     = blockIdx.y * 8 + warp;
    int kbase = blockIdx.x * 16;

    const unsigned long long* Tm =
        reinterpret_cast<const unsigned long long*>(g_T + b * HDIM);                // -tanh pairs
    const unsigned long long* Tp =
        reinterpret_cast<const unsigned long long*>(g_T + BDIM * HDIM + b * HDIM);  // +tanh pairs

    for (int kk = 0; kk < 16; kk++) {
        __syncthreads();   // keep warps in lockstep on k for CS L1 reuse
        int k = kbase + kk;
        float sgn = x[b * NDIM + k];
        const unsigned long long* Trow = (sgn > 0.0f) ? Tm : Tp;
        const ulonglong2* CS = g_CS + k * HP;

        unsigned long long acc0 = pk2(1.0f, 1.0f);
        unsigned long long acc1 = pk2(1.0f, 1.0f);
#pragma unroll
        for (int i = 0; i < 32; i += 2) {
            int hpA = i * 32 + lane;
            int hpB = (i + 1) * 32 + lane;
            ulonglong2 csA = CS[hpA];               // LDG.128: (C0,C1,S0,S1)
            unsigned long long tA = Trow[hpA];      // LDG.64: (-s*t0, -s*t1)
            ulonglong2 csB = CS[hpB];
            unsigned long long tB = Trow[hpB];
            acc0 = mul2(acc0, fma2(tA, csA.y, csA.x));  // r = C + (-s*t)*S
            acc1 = mul2(acc1, fma2(tB, csB.y, csB.x));
        }
        float2 a0 = up2(acc0), a1 = up2(acc1);
        float p = (a0.x * a0.y) * (a1.x * a1.y);
#pragma unroll
        for (int o = 16; o; o >>= 1)
            p *= __shfl_xor_sync(0xffffffffu, p, o);
        if (lane == 0) g_P[b * NDIM + k] = p;
    }
}

// ---------------------------------------------------------------------------
// Kernel 5: out[b] = sum_k Oxy[k] * exp(-2*x[b,k]*a[k]) * P[b,k]
// grid BDIM, block 512
// ---------------------------------------------------------------------------
__global__ void __launch_bounds__(512) reduce_kernel(const float* __restrict__ x,
                                                     const float* __restrict__ a,
                                                     const float* __restrict__ Oxy,
                                                     float* __restrict__ out) {
    int b = blockIdx.x;
    int t = threadIdx.x;   // == k
    float v = g_P[b * NDIM + t] * Oxy[t] * expf(-2.0f * x[b * NDIM + t] * a[t]);

    __shared__ float smem[16];
#pragma unroll
    for (int o = 16; o; o >>= 1) v += __shfl_xor_sync(0xffffffffu, v, o);
    if ((t & 31) == 0) smem[t >> 5] = v;
    __syncthreads();
    if (t < 16) {
        float v2 = smem[t];
#pragma unroll
        for (int o = 8; o; o >>= 1) v2 += __shfl_xor_sync(0x0000ffffu, v2, o);
        if (t == 0) out[b] = v2;
    }
}

// ---------------------------------------------------------------------------
// Launch
// ---------------------------------------------------------------------------
extern "C" void kernel_launch(void* const* d_in, const int* in_sizes, int n_in,
                              void* d_out, int out_size) {
    const float* x    = (const float*)d_in[0];   // [64,512]
    const float* W    = (const float*)d_in[1];   // [512,2048]
    const float* bias = (const float*)d_in[2];   // [2048]
    const float* a    = (const float*)d_in[3];   // [512]
    const float* Oxy  = (const float*)d_in[4];   // [512]
    float* out = (float*)d_out;                  // [64]

    prep_cs_kernel<<<(NDIM * HP + 255) / 256, 256>>>(W);
    xpose_kernel<<<(BDIM * NDIM + 255) / 256, 256>>>(x);
    z_tanh_kernel<<<dim3(HDIM / 256, BDIM / 4), 256>>>(W, bias);
    prod_kernel<<<dim3(NDIM / 16, BDIM / 8), 256>>>(x);
    reduce_kernel<<<BDIM, 512>>>(x, a, Oxy, out);
}

// round 2
// speedup vs baseline: 2.1735x; 2.1735x over previous
#include <cuda_runtime.h>

// Problem dims (fixed by the dataset)
#define BDIM 64
#define NDIM 512
#define HDIM 2048
#define KP   (NDIM / 2)    // 256 packed k-pairs
#define HC   128           // h-chunk size for prod kernel
#define NCHUNK (HDIM / HC) // 16 partial-product chunks

// ---------------------------------------------------------------------------
// Device scratch (allocation-free rule: __device__ globals)
// ---------------------------------------------------------------------------
__device__ ulonglong2 g_CS2[HDIM * KP];        // [h][kp]: .x = pk2(C[2kp][h],C[2kp+1][h]), .y = same for S;  C=cosh(2W), S=sinh(2W)
__device__ float      g_Tt[HDIM * BDIM];       // [h][b] = tanh(z[b][h])
__device__ unsigned long long g_negx2[BDIM * KP]; // [b][kp] = pk2(-x[b][2kp], -x[b][2kp+1])
__device__ float      g_xT[NDIM * BDIM];       // x transposed: [n][b]
__device__ float2     g_Ppart[NCHUNK * BDIM * KP]; // [chunk][b][kp] partial products (lo=k even, hi=k odd)

// ---------------------------------------------------------------------------
// f32x2 packed helpers
// ---------------------------------------------------------------------------
__device__ __forceinline__ unsigned long long pk2(float lo, float hi) {
    unsigned long long r;
    asm("mov.b64 %0, {%1, %2};" : "=l"(r) : "f"(lo), "f"(hi));
    return r;
}
__device__ __forceinline__ unsigned long long fma2(unsigned long long a, unsigned long long b, unsigned long long c) {
    unsigned long long r;
    asm("fma.rn.f32x2 %0, %1, %2, %3;" : "=l"(r) : "l"(a), "l"(b), "l"(c));
    return r;
}
__device__ __forceinline__ unsigned long long mul2(unsigned long long a, unsigned long long b) {
    unsigned long long r;
    asm("mul.rn.f32x2 %0, %1, %2;" : "=l"(r) : "l"(a), "l"(b));
    return r;
}
__device__ __forceinline__ float2 up2(unsigned long long p) {
    float lo, hi;
    asm("mov.b64 {%0, %1}, %2;" : "=f"(lo), "=f"(hi) : "l"(p));
    return make_float2(lo, hi);
}

// ---------------------------------------------------------------------------
// Kernel 1: C/S precompute, h-major, packed over k-pairs.
// grid (KP, HDIM/256), block 256. Coalesced W reads, 16B scattered CS2 writes.
// ---------------------------------------------------------------------------
__global__ void __launch_bounds__(256) prep_cs_kernel(const float* __restrict__ W) {
    int kp = blockIdx.x;
    int h  = blockIdx.y * 256 + threadIdx.x;
    float w0 = __ldg(W + (2 * kp)     * HDIM + h);
    float w1 = __ldg(W + (2 * kp + 1) * HDIM + h);
    float c0 = coshf(2.0f * w0), s0 = sinhf(2.0f * w0);
    float c1 = coshf(2.0f * w1), s1 = sinhf(2.0f * w1);
    g_CS2[h * KP + kp] = make_ulonglong2(pk2(c0, c1), pk2(s0, s1));
}

// ---------------------------------------------------------------------------
// Kernel 2: x-derived precompute: negx2 and xT. grid 192, block 256.
// ---------------------------------------------------------------------------
__global__ void __launch_bounds__(256) prep_x_kernel(const float* __restrict__ x) {
    int idx = blockIdx.x * 256 + threadIdx.x;
    if (idx < BDIM * KP) {                       // negx2
        int b = idx >> 8, kp = idx & 255;
        float x0 = x[b * NDIM + 2 * kp];
        float x1 = x[b * NDIM + 2 * kp + 1];
        g_negx2[idx] = pk2(-x0, -x1);
    } else {                                      // xT
        int j = idx - BDIM * KP;                  // 0 .. 32767
        int n = j >> 6, b = j & 63;
        g_xT[n * BDIM + b] = x[b * NDIM + n];
    }
}

// ---------------------------------------------------------------------------
// Kernel 3: z = x@W + bias, Tt[h][b] = tanh(z).
// Thread = (1 h, 4 b). grid (HDIM/256, BDIM/4) = 128 blocks, block 256.
// ---------------------------------------------------------------------------
__global__ void __launch_bounds__(256) z_tanh_kernel(const float* __restrict__ W,
                                                     const float* __restrict__ bias) {
    int h  = blockIdx.x * 256 + threadIdx.x;
    int b0 = blockIdx.y * 4;
    float bv = bias[h];
    float z0 = bv, z1 = bv, z2 = bv, z3 = bv;
    const float*  wp = W + h;
    const float4* xp = reinterpret_cast<const float4*>(g_xT + b0);
#pragma unroll 16
    for (int n = 0; n < NDIM; n++) {
        float  w  = __ldg(wp + n * HDIM);          // coalesced across threads
        float4 xv = xp[n * (BDIM / 4)];            // block-uniform broadcast
        z0 = fmaf(xv.x, w, z0);
        z1 = fmaf(xv.y, w, z1);
        z2 = fmaf(xv.z, w, z2);
        z3 = fmaf(xv.w, w, z3);
    }
    float4 t = make_float4(tanhf(z0), tanhf(z1), tanhf(z2), tanhf(z3));
    *reinterpret_cast<float4*>(g_Tt + h * BDIM + b0) = t;
}

// ---------------------------------------------------------------------------
// Kernel 4: main product kernel.
//   Ppart[c][b][k] = prod_{h in chunk c} ( C[k,h] - x[b,k]*tanh(z[b,h])*S[k,h] )
// Thread tile: 1 kp (2 k) x 4 b; warp = 32 kp x 4 b; block = 32 kp x 32 b.
// grid (KP/32, BDIM/32, NCHUNK) = (8, 2, 16), block 256.
// One CS LDG.128 feeds 8 outputs; T comes as one uniform float4 per h.
// ---------------------------------------------------------------------------
__global__ void __launch_bounds__(256) prod_kernel() {
    int lane = threadIdx.x & 31;
    int w    = threadIdx.x >> 5;
    int kp   = blockIdx.x * 32 + lane;
    int b0   = blockIdx.y * 32 + w * 4;
    int h0   = blockIdx.z * HC;

    unsigned long long nx0 = g_negx2[(b0 + 0) * KP + kp];
    unsigned long long nx1 = g_negx2[(b0 + 1) * KP + kp];
    unsigned long long nx2 = g_negx2[(b0 + 2) * KP + kp];
    unsigned long long nx3 = g_negx2[(b0 + 3) * KP + kp];

    const ulonglong2* cs = g_CS2 + (size_t)h0 * KP + kp;
    const float4*     tp = reinterpret_cast<const float4*>(g_Tt + h0 * BDIM + b0);

    unsigned long long acc0 = pk2(1.0f, 1.0f);
    unsigned long long acc1 = pk2(1.0f, 1.0f);
    unsigned long long acc2 = pk2(1.0f, 1.0f);
    unsigned long long acc3 = pk2(1.0f, 1.0f);

#pragma unroll 4
    for (int h = 0; h < HC; h++) {
        ulonglong2 csv = __ldg(cs + h * KP);            // {C pair, S pair}
        float4     tv  = __ldg(tp + h * (BDIM / 4));    // tanh for 4 b (uniform)
        acc0 = mul2(acc0, fma2(mul2(nx0, pk2(tv.x, tv.x)), csv.y, csv.x));
        acc1 = mul2(acc1, fma2(mul2(nx1, pk2(tv.y, tv.y)), csv.y, csv.x));
        acc2 = mul2(acc2, fma2(mul2(nx2, pk2(tv.z, tv.z)), csv.y, csv.x));
        acc3 = mul2(acc3, fma2(mul2(nx3, pk2(tv.w, tv.w)), csv.y, csv.x));
    }

    float2* out = g_Ppart + blockIdx.z * (BDIM * KP);
    out[(b0 + 0) * KP + kp] = up2(acc0);
    out[(b0 + 1) * KP + kp] = up2(acc1);
    out[(b0 + 2) * KP + kp] = up2(acc2);
    out[(b0 + 3) * KP + kp] = up2(acc3);
}

// ---------------------------------------------------------------------------
// Kernel 5: out[b] = sum_k Oxy[k]*exp(-2*x[b,k]*a[k]) * prod_c Ppart[c][b][k]
// grid BDIM, block 512 (thread == k)
// ---------------------------------------------------------------------------
__global__ void __launch_bounds__(512) reduce_kernel(const float* __restrict__ x,
                                                     const float* __restrict__ a,
                                                     const float* __restrict__ Oxy,
                                                     float* __restrict__ out) {
    int b = blockIdx.x;
    int k = threadIdx.x;
    const float* P = reinterpret_cast<const float*>(g_Ppart) + b * NDIM + k;
    float p = 1.0f;
#pragma unroll
    for (int c = 0; c < NCHUNK; c++)
        p *= __ldg(P + c * (BDIM * NDIM));
    float v = p * Oxy[k] * expf(-2.0f * x[b * NDIM + k] * a[k]);

    __shared__ float smem[16];
#pragma unroll
    for (int o = 16; o; o >>= 1) v += __shfl_xor_sync(0xffffffffu, v, o);
    if ((k & 31) == 0) smem[k >> 5] = v;
    __syncthreads();
    if (k < 16) {
        float v2 = smem[k];
#pragma unroll
        for (int o = 8; o; o >>= 1) v2 += __shfl_xor_sync(0x0000ffffu, v2, o);
        if (k == 0) out[b] = v2;
    }
}

// ---------------------------------------------------------------------------
// Launch
// ---------------------------------------------------------------------------
extern "C" void kernel_launch(void* const* d_in, const int* in_sizes, int n_in,
                              void* d_out, int out_size) {
    const float* x    = (const float*)d_in[0];   // [64,512]
    const float* W    = (const float*)d_in[1];   // [512,2048]
    const float* bias = (const float*)d_in[2];   // [2048]
    const float* a    = (const float*)d_in[3];   // [512]
    const float* Oxy  = (const float*)d_in[4];   // [512]
    float* out = (float*)d_out;                  // [64]

    prep_cs_kernel<<<dim3(KP, HDIM / 256), 256>>>(W);
    prep_x_kernel<<<(BDIM * KP + NDIM * BDIM + 255) / 256, 256>>>(x);
    z_tanh_kernel<<<dim3(HDIM / 256, BDIM / 4), 256>>>(W, bias);
    prod_kernel<<<dim3(KP / 32, BDIM / 32, NCHUNK), 256>>>();
    reduce_kernel<<<BDIM, 512>>>(x, a, Oxy, out);
}

// round 3
// speedup vs baseline: 3.8034x; 1.7498x over previous
#include <cuda_runtime.h>

// Problem dims (fixed by the dataset)
#define BDIM 64
#define NDIM 512
#define HDIM 2048
#define KP     (NDIM / 2)     // 256 packed k-pairs
#define HC     32             // h-chunk per prod block
#define NCHUNK (HDIM / HC)    // 64 partial-product chunks
#define NSPLIT 8              // n-split for z-GEMM
#define NCK    (NDIM / NSPLIT)

// ---------------------------------------------------------------------------
// Device scratch (allocation-free rule: __device__ globals)
// ---------------------------------------------------------------------------
__device__ ulonglong2 g_CS2[HDIM * KP];              // [h][kp]: {pk2(C0,C1), pk2(S0,S1)}, C=cosh(2W), S=sinh(2W)
__device__ float      g_Tt[HDIM * BDIM];             // [h][b] = tanh(z[b][h])
__device__ unsigned long long g_negx2[BDIM * KP];    // [b][kp] = pk2(-x[b][2kp], -x[b][2kp+1])
__device__ unsigned long long g_x2[NDIM * (BDIM/2)]; // [n][bp] = pk2(x[2bp][n], x[2bp+1][n])
__device__ float      g_ea[BDIM * NDIM];             // [b][k] = Oxy[k]*exp(-2*x[b,k]*a[k])
__device__ unsigned long long g_zp[NSPLIT * HDIM * (BDIM/2)]; // z partials [ns][h][bp] packed
__device__ unsigned long long g_Ppart[NCHUNK * BDIM * KP];    // [c][b][kp] partial products packed

// ---------------------------------------------------------------------------
// f32x2 packed helpers
// ---------------------------------------------------------------------------
__device__ __forceinline__ unsigned long long pk2(float lo, float hi) {
    unsigned long long r;
    asm("mov.b64 %0, {%1, %2};" : "=l"(r) : "f"(lo), "f"(hi));
    return r;
}
__device__ __forceinline__ unsigned long long fma2(unsigned long long a, unsigned long long b, unsigned long long c) {
    unsigned long long r;
    asm("fma.rn.f32x2 %0, %1, %2, %3;" : "=l"(r) : "l"(a), "l"(b), "l"(c));
    return r;
}
__device__ __forceinline__ unsigned long long mul2(unsigned long long a, unsigned long long b) {
    unsigned long long r;
    asm("mul.rn.f32x2 %0, %1, %2;" : "=l"(r) : "l"(a), "l"(b));
    return r;
}
__device__ __forceinline__ unsigned long long add2(unsigned long long a, unsigned long long b) {
    unsigned long long r;
    asm("add.rn.f32x2 %0, %1, %2;" : "=l"(r) : "l"(a), "l"(b));
    return r;
}
__device__ __forceinline__ float2 up2(unsigned long long p) {
    float lo, hi;
    asm("mov.b64 {%0, %1}, %2;" : "=f"(lo), "=f"(hi) : "l"(p));
    return make_float2(lo, hi);
}

// ---------------------------------------------------------------------------
// Kernel 1: C/S precompute via smem transpose.
// Tile: 64 k (=32 kp) x 32 h. Coalesced W reads AND coalesced CS2 writes.
// grid (NDIM/64, HDIM/32) = (8, 64), block 256.
// ---------------------------------------------------------------------------
__global__ void __launch_bounds__(256) prep_cs_kernel(const float* __restrict__ W) {
    __shared__ float sc[32 * 64];  // [h_local][k_local]
    __shared__ float ss[32 * 64];
    int k0 = blockIdx.x * 64;
    int h0 = blockIdx.y * 32;
    int tx = threadIdx.x;
#pragma unroll
    for (int j = 0; j < 8; j++) {
        int idx = tx + j * 256;          // 0..2047
        int kl = idx >> 5, hl = idx & 31;
        float w  = __ldg(W + (k0 + kl) * HDIM + h0 + hl);
        float e  = __expf(2.0f * w);
        float ei = __expf(-2.0f * w);
        sc[hl * 64 + kl] = 0.5f * (e + ei);
        ss[hl * 64 + kl] = 0.5f * (e - ei);
    }
    __syncthreads();
#pragma unroll
    for (int j = 0; j < 4; j++) {
        int idx = tx + j * 256;          // 0..1023 over 32h x 32kp
        int hl = idx >> 5, kpl = idx & 31;
        float c0 = sc[hl * 64 + 2 * kpl], c1 = sc[hl * 64 + 2 * kpl + 1];
        float s0 = ss[hl * 64 + 2 * kpl], s1 = ss[hl * 64 + 2 * kpl + 1];
        g_CS2[(h0 + hl) * KP + (k0 >> 1) + kpl] = make_ulonglong2(pk2(c0, c1), pk2(s0, s1));
    }
}

// ---------------------------------------------------------------------------
// Kernel 2: x-derived precompute: negx2, x2, ea. grid 128, block 256.
// ---------------------------------------------------------------------------
__global__ void __launch_bounds__(256) prep_x_kernel(const float* __restrict__ x,
                                                     const float* __restrict__ a,
                                                     const float* __restrict__ Oxy) {
    int idx = blockIdx.x * 256 + threadIdx.x;      // 0..32767
    {   // ea
        int b = idx >> 9, k = idx & 511;
        g_ea[idx] = Oxy[k] * __expf(-2.0f * x[b * NDIM + k] * a[k]);
    }
    if (idx < BDIM * KP) {                          // negx2 [b][kp]
        int b = idx >> 8, kp = idx & 255;
        g_negx2[idx] = pk2(-x[b * NDIM + 2 * kp], -x[b * NDIM + 2 * kp + 1]);
    }
    if (idx < NDIM * (BDIM / 2)) {                  // x2 [n][bp]
        int n = idx >> 5, bp = idx & 31;
        g_x2[idx] = pk2(x[(2 * bp) * NDIM + n], x[(2 * bp + 1) * NDIM + n]);
    }
}

// ---------------------------------------------------------------------------
// Kernel 3: z partials. Thread = (1 h, 8 b as 4 packed accs), n-chunk NCK.
// grid (HDIM/256, BDIM/8, NSPLIT) = (8, 8, 8) = 512 blocks, block 256.
// ---------------------------------------------------------------------------
__global__ void __launch_bounds__(256) z_part_kernel(const float* __restrict__ W) {
    int h   = blockIdx.x * 256 + threadIdx.x;
    int bp0 = blockIdx.y * 4;
    int n0  = blockIdx.z * NCK;
    unsigned long long a0 = 0, a1 = 0, a2 = 0, a3 = 0;  // +0.0 packed
    const float* wp = W + (size_t)n0 * HDIM + h;
    const ulonglong2* xp = reinterpret_cast<const ulonglong2*>(g_x2 + n0 * 32 + bp0);
#pragma unroll 4
    for (int n = 0; n < NCK; n++) {
        float w = __ldg(wp + n * HDIM);          // coalesced across threads
        unsigned long long wd = pk2(w, w);
        ulonglong2 xA = __ldg(xp + n * 16);      // bp0, bp0+1 (uniform)
        ulonglong2 xB = __ldg(xp + n * 16 + 1);  // bp0+2, bp0+3 (uniform)
        a0 = fma2(xA.x, wd, a0);
        a1 = fma2(xA.y, wd, a1);
        a2 = fma2(xB.x, wd, a2);
        a3 = fma2(xB.y, wd, a3);
    }
    ulonglong2* zp = reinterpret_cast<ulonglong2*>(g_zp + ((size_t)blockIdx.z * HDIM + h) * 32 + bp0);
    zp[0] = make_ulonglong2(a0, a1);
    zp[1] = make_ulonglong2(a2, a3);
}

// ---------------------------------------------------------------------------
// Kernel 4: combine z partials + bias, tanh, write Tt[h][b].
// grid 256, block 256 (thread = (h, bp)).
// ---------------------------------------------------------------------------
__global__ void __launch_bounds__(256) z_comb_kernel(const float* __restrict__ bias) {
    int idx = blockIdx.x * 256 + threadIdx.x;   // 0..65535
    int h = idx >> 5, bp = idx & 31;
    unsigned long long s = 0;
#pragma unroll
    for (int ns = 0; ns < NSPLIT; ns++)
        s = add2(s, __ldg(g_zp + ((size_t)ns * HDIM + h) * 32 + bp));
    float2 z = up2(s);
    float bv = bias[h];
    float2 t = make_float2(tanhf(z.x + bv), tanhf(z.y + bv));
    *reinterpret_cast<float2*>(g_Tt + h * BDIM + 2 * bp) = t;
}

// ---------------------------------------------------------------------------
// Kernel 5: main product kernel.
//   Ppart[c][b][k] = prod_{h in chunk c} ( C[k,h] - x[b,k]*tanh(z[b,h])*S[k,h] )
// Thread tile: 1 kp (2 k) x 8 b; warp = 32 kp x 8 b; block = 8 warps = all 64 b.
// grid (KP/32, 1, NCHUNK) = (8, 1, 64) = 512 blocks, block 256.
// ---------------------------------------------------------------------------
__global__ void __launch_bounds__(256, 2) prod_kernel() {
    int lane = threadIdx.x & 31;
    int w    = threadIdx.x >> 5;
    int kp   = blockIdx.x * 32 + lane;
    int b0   = w * 8;
    int h0   = blockIdx.z * HC;

    unsigned long long nx[8];
#pragma unroll
    for (int i = 0; i < 8; i++)
        nx[i] = g_negx2[(b0 + i) * KP + kp];

    const ulonglong2* cs = g_CS2 + (size_t)h0 * KP + kp;
    const float4*     tp = reinterpret_cast<const float4*>(g_Tt + h0 * BDIM + b0);

    unsigned long long acc[8];
#pragma unroll
    for (int i = 0; i < 8; i++) acc[i] = pk2(1.0f, 1.0f);

#pragma unroll 4
    for (int h = 0; h < HC; h++) {
        ulonglong2 csv = __ldg(cs + h * KP);            // {C pair, S pair}
        float4 ta = __ldg(tp + h * (BDIM / 4));         // tanh for b0..b0+3 (uniform)
        float4 tb = __ldg(tp + h * (BDIM / 4) + 1);     // tanh for b0+4..b0+7
        acc[0] = mul2(acc[0], fma2(mul2(nx[0], pk2(ta.x, ta.x)), csv.y, csv.x));
        acc[1] = mul2(acc[1], fma2(mul2(nx[1], pk2(ta.y, ta.y)), csv.y, csv.x));
        acc[2] = mul2(acc[2], fma2(mul2(nx[2], pk2(ta.z, ta.z)), csv.y, csv.x));
        acc[3] = mul2(acc[3], fma2(mul2(nx[3], pk2(ta.w, ta.w)), csv.y, csv.x));
        acc[4] = mul2(acc[4], fma2(mul2(nx[4], pk2(tb.x, tb.x)), csv.y, csv.x));
        acc[5] = mul2(acc[5], fma2(mul2(nx[5], pk2(tb.y, tb.y)), csv.y, csv.x));
        acc[6] = mul2(acc[6], fma2(mul2(nx[6], pk2(tb.z, tb.z)), csv.y, csv.x));
        acc[7] = mul2(acc[7], fma2(mul2(nx[7], pk2(tb.w, tb.w)), csv.y, csv.x));
    }

    unsigned long long* out = g_Ppart + (size_t)blockIdx.z * (BDIM * KP);
#pragma unroll
    for (int i = 0; i < 8; i++)
        out[(b0 + i) * KP + kp] = acc[i];
}

// ---------------------------------------------------------------------------
// Kernel 6: out[b] = sum_k ea[b,k] * prod_c Ppart[c][b][k]
// grid BDIM, block 256 (thread = kp)
// ---------------------------------------------------------------------------
__global__ void __launch_bounds__(256) reduce_kernel(float* __restrict__ out) {
    int b  = blockIdx.x;
    int kp = threadIdx.x;
    const unsigned long long* P = g_Ppart + b * KP + kp;
    unsigned long long p = pk2(1.0f, 1.0f);
#pragma unroll 8
    for (int c = 0; c < NCHUNK; c++)
        p = mul2(p, __ldg(P + (size_t)c * (BDIM * KP)));
    float2 pf = up2(p);
    float2 ea = *reinterpret_cast<const float2*>(g_ea + b * NDIM + 2 * kp);
    float v = pf.x * ea.x + pf.y * ea.y;

    __shared__ float smem[8];
#pragma unroll
    for (int o = 16; o; o >>= 1) v += __shfl_xor_sync(0xffffffffu, v, o);
    if ((kp & 31) == 0) smem[kp >> 5] = v;
    __syncthreads();
    if (kp < 8) {
        float v2 = smem[kp];
#pragma unroll
        for (int o = 4; o; o >>= 1) v2 += __shfl_xor_sync(0x000000ffu, v2, o);
        if (kp == 0) out[b] = v2;
    }
}

// ---------------------------------------------------------------------------
// Launch
// ---------------------------------------------------------------------------
extern "C" void kernel_launch(void* const* d_in, const int* in_sizes, int n_in,
                              void* d_out, int out_size) {
    const float* x    = (const float*)d_in[0];   // [64,512]
    const float* W    = (const float*)d_in[1];   // [512,2048]
    const float* bias = (const float*)d_in[2];   // [2048]
    const float* a    = (const float*)d_in[3];   // [512]
    const float* Oxy  = (const float*)d_in[4];   // [512]
    float* out = (float*)d_out;                  // [64]

    prep_cs_kernel<<<dim3(NDIM / 64, HDIM / 32), 256>>>(W);
    prep_x_kernel<<<128, 256>>>(x, a, Oxy);
    z_part_kernel<<<dim3(HDIM / 256, BDIM / 8, NSPLIT), 256>>>(W);
    z_comb_kernel<<<256, 256>>>(bias);
    prod_kernel<<<dim3(KP / 32, 1, NCHUNK), 256>>>();
    reduce_kernel<<<BDIM, 256>>>(out);
}

// round 4
// speedup vs baseline: 6.0010x; 1.5778x over previous
#include <cuda_runtime.h>

// Problem dims (fixed by the dataset)
#define BDIM 64
#define NDIM 512
#define HDIM 2048
#define KP     (NDIM / 2)     // 256 packed k-pairs
#define HC     32             // h-chunk per prod block
#define NCHUNK (HDIM / HC)    // 64 partial-product chunks
#define NSPLIT 8              // n-split for z-GEMM
#define NCK    (NDIM / NSPLIT)

// ---------------------------------------------------------------------------
// Device scratch (allocation-free rule: __device__ globals)
// ---------------------------------------------------------------------------
__device__ float              g_Tt[HDIM * BDIM];                  // [h][b] = tanh(z[b][h])
__device__ unsigned long long g_zp[NSPLIT * HDIM * (BDIM / 2)];   // z partials [ns][h][bp] packed
__device__ unsigned long long g_Ppart[NCHUNK * BDIM * KP];        // [c][b][kp] partial ratio-products packed

// ---------------------------------------------------------------------------
// f32x2 packed helpers
// ---------------------------------------------------------------------------
__device__ __forceinline__ unsigned long long pk2(float lo, float hi) {
    unsigned long long r;
    asm("mov.b64 %0, {%1, %2};" : "=l"(r) : "f"(lo), "f"(hi));
    return r;
}
__device__ __forceinline__ unsigned long long fma2(unsigned long long a, unsigned long long b, unsigned long long c) {
    unsigned long long r;
    asm("fma.rn.f32x2 %0, %1, %2, %3;" : "=l"(r) : "l"(a), "l"(b), "l"(c));
    return r;
}
__device__ __forceinline__ unsigned long long mul2(unsigned long long a, unsigned long long b) {
    unsigned long long r;
    asm("mul.rn.f32x2 %0, %1, %2;" : "=l"(r) : "l"(a), "l"(b));
    return r;
}
__device__ __forceinline__ unsigned long long add2(unsigned long long a, unsigned long long b) {
    unsigned long long r;
    asm("add.rn.f32x2 %0, %1, %2;" : "=l"(r) : "l"(a), "l"(b));
    return r;
}
__device__ __forceinline__ float2 up2(unsigned long long p) {
    float lo, hi;
    asm("mov.b64 {%0, %1}, %2;" : "=f"(lo), "=f"(hi) : "l"(p));
    return make_float2(lo, hi);
}

// ---------------------------------------------------------------------------
// Kernel 1: z partials. Thread = (1 h, 8 b as 4 packed accs), n-chunk NCK.
// x staged in smem by the block itself (no prep kernel).
// grid (HDIM/256, BDIM/8, NSPLIT) = (8, 8, 8) = 512 blocks, block 256.
// ---------------------------------------------------------------------------
__global__ void __launch_bounds__(256) z_part_kernel(const float* __restrict__ W,
                                                     const float* __restrict__ x) {
    __shared__ float sx[NCK][8];   // [n_local][b_local]
    int t  = threadIdx.x;
    int h  = blockIdx.x * 256 + t;
    int b0 = blockIdx.y * 8;
    int n0 = blockIdx.z * NCK;

#pragma unroll
    for (int j = 0; j < 2; j++) {
        int idx = t + j * 256;               // 0..511
        int bl = idx >> 6, nl = idx & 63;
        sx[nl][bl] = __ldg(x + (size_t)(b0 + bl) * NDIM + n0 + nl);
    }
    __syncthreads();

    unsigned long long a0 = 0, a1 = 0, a2 = 0, a3 = 0;   // packed +0.0
    const float* wp = W + (size_t)n0 * HDIM + h;
#pragma unroll 4
    for (int n = 0; n < NCK; n++) {
        float w = __ldg(wp + n * HDIM);                  // coalesced across threads
        unsigned long long wd = pk2(w, w);
        const ulonglong2* xr = reinterpret_cast<const ulonglong2*>(&sx[n][0]);
        ulonglong2 xA = xr[0];                           // b0+0..3 (uniform broadcast)
        ulonglong2 xB = xr[1];                           // b0+4..7
        a0 = fma2(xA.x, wd, a0);
        a1 = fma2(xA.y, wd, a1);
        a2 = fma2(xB.x, wd, a2);
        a3 = fma2(xB.y, wd, a3);
    }
    int bp0 = blockIdx.y * 4;
    ulonglong2* zp = reinterpret_cast<ulonglong2*>(
        g_zp + ((size_t)blockIdx.z * HDIM + h) * (BDIM / 2) + bp0);
    zp[0] = make_ulonglong2(a0, a1);
    zp[1] = make_ulonglong2(a2, a3);
}

// ---------------------------------------------------------------------------
// Kernel 2: combine z partials + bias, tanh, write Tt[h][b].
// grid 256, block 256 (thread = (h, bp)); 2 independent add chains for MLP.
// ---------------------------------------------------------------------------
__global__ void __launch_bounds__(256) z_comb_kernel(const float* __restrict__ bias) {
    int idx = blockIdx.x * 256 + threadIdx.x;   // 0..65535
    int h = idx >> 5, bp = idx & 31;
    const unsigned long long* zp = g_zp + (size_t)h * (BDIM / 2) + bp;
    unsigned long long s0 = 0, s1 = 0;
#pragma unroll
    for (int ns = 0; ns < NSPLIT; ns += 2) {
        s0 = add2(s0, __ldg(zp + (size_t)ns * (HDIM * BDIM / 2)));
        s1 = add2(s1, __ldg(zp + (size_t)(ns + 1) * (HDIM * BDIM / 2)));
    }
    float2 z = up2(add2(s0, s1));
    float bv = bias[h];
    float2 tv = make_float2(tanhf(z.x + bv), tanhf(z.y + bv));
    *reinterpret_cast<float2*>(g_Tt + (size_t)h * BDIM + 2 * bp) = tv;
}

// ---------------------------------------------------------------------------
// Kernel 3: main product kernel with fused C/S generation.
//   Ppart[c][b][k] = prod_{h in chunk} ( cosh(2W[k,h]) - x[b,k]*tanh(z[b,h])*sinh(2W[k,h]) )
// Prologue: block builds its (32h x 64k) C/S tile in smem from W (expf), and
// loads/negates its x signs. Thread tile: 1 kp (2 k) x 8 b.
// grid (KP/32, 1, NCHUNK) = (8, 1, 64) = 512 blocks, block 256, 3 blocks/SM.
// ---------------------------------------------------------------------------
__global__ void __launch_bounds__(256, 3) prod_kernel(const float* __restrict__ W,
                                                      const float* __restrict__ x) {
    __shared__ float sC[HC][66];   // pad 66: conflict-free stores & LDS.64 reads
    __shared__ float sS[HC][66];
    int t    = threadIdx.x;
    int lane = t & 31;
    int w    = t >> 5;
    int k0   = blockIdx.x * 64;    // 64 k = 32 kp per block
    int h0   = blockIdx.z * HC;

    // Build C/S tile: coalesced W reads (lane -> h), MUFU expf
#pragma unroll
    for (int j = 0; j < 8; j++) {
        int idx = t + j * 256;                // 0..2047
        int hl = idx & 31, kl = idx >> 5;
        float wv = __ldg(W + (size_t)(k0 + kl) * HDIM + h0 + hl);
        float e  = __expf(2.0f * wv);
        float ei = __expf(-2.0f * wv);
        sC[hl][kl] = 0.5f * (e + ei);
        sS[hl][kl] = 0.5f * (e - ei);
    }

    // -x signs for 8 b at this thread's kp (coalesced LDG.64, XOR sign flip)
    int b0 = w * 8;
    unsigned long long nx[8];
#pragma unroll
    for (int i = 0; i < 8; i++) {
        unsigned long long xv = *reinterpret_cast<const unsigned long long*>(
            x + (size_t)(b0 + i) * NDIM + k0 + 2 * lane);
        nx[i] = xv ^ 0x8000000080000000ULL;
    }
    __syncthreads();

    const float4* tp = reinterpret_cast<const float4*>(g_Tt + (size_t)h0 * BDIM + b0);

    unsigned long long acc[8];
#pragma unroll
    for (int i = 0; i < 8; i++) acc[i] = pk2(1.0f, 1.0f);

#pragma unroll 4
    for (int h = 0; h < HC; h++) {
        unsigned long long Cp = *reinterpret_cast<const unsigned long long*>(&sC[h][2 * lane]);
        unsigned long long Sp = *reinterpret_cast<const unsigned long long*>(&sS[h][2 * lane]);
        float4 ta = __ldg(tp + h * (BDIM / 4));       // tanh b0..b0+3 (uniform)
        float4 tb = __ldg(tp + h * (BDIM / 4) + 1);   // tanh b0+4..b0+7
        acc[0] = mul2(acc[0], fma2(mul2(nx[0], pk2(ta.x, ta.x)), Sp, Cp));
        acc[1] = mul2(acc[1], fma2(mul2(nx[1], pk2(ta.y, ta.y)), Sp, Cp));
        acc[2] = mul2(acc[2], fma2(mul2(nx[2], pk2(ta.z, ta.z)), Sp, Cp));
        acc[3] = mul2(acc[3], fma2(mul2(nx[3], pk2(ta.w, ta.w)), Sp, Cp));
        acc[4] = mul2(acc[4], fma2(mul2(nx[4], pk2(tb.x, tb.x)), Sp, Cp));
        acc[5] = mul2(acc[5], fma2(mul2(nx[5], pk2(tb.y, tb.y)), Sp, Cp));
        acc[6] = mul2(acc[6], fma2(mul2(nx[6], pk2(tb.z, tb.z)), Sp, Cp));
        acc[7] = mul2(acc[7], fma2(mul2(nx[7], pk2(tb.w, tb.w)), Sp, Cp));
    }

    int kp = blockIdx.x * 32 + lane;
    unsigned long long* out = g_Ppart + (size_t)blockIdx.z * (BDIM * KP);
#pragma unroll
    for (int i = 0; i < 8; i++)
        out[(size_t)(b0 + i) * KP + kp] = acc[i];
}

// ---------------------------------------------------------------------------
// Kernel 4: out[b] = sum_k Oxy[k]*exp(-2*x[b,k]*a[k]) * prod_c Ppart[c][b][k]
// ea computed inline. grid BDIM, block 256 (thread = kp), 2 product chains.
// ---------------------------------------------------------------------------
__global__ void __launch_bounds__(256) reduce_kernel(const float* __restrict__ x,
                                                     const float* __restrict__ a,
                                                     const float* __restrict__ Oxy,
                                                     float* __restrict__ out) {
    int b  = blockIdx.x;
    int kp = threadIdx.x;
    const unsigned long long* P = g_Ppart + (size_t)b * KP + kp;
    unsigned long long p0 = pk2(1.0f, 1.0f), p1 = pk2(1.0f, 1.0f);
#pragma unroll 8
    for (int c = 0; c < NCHUNK; c += 2) {
        p0 = mul2(p0, __ldg(P + (size_t)c * (BDIM * KP)));
        p1 = mul2(p1, __ldg(P + (size_t)(c + 1) * (BDIM * KP)));
    }
    float2 pf = up2(mul2(p0, p1));
    float2 xv = *reinterpret_cast<const float2*>(x + (size_t)b * NDIM + 2 * kp);
    float2 av = *reinterpret_cast<const float2*>(a + 2 * kp);
    float2 ov = *reinterpret_cast<const float2*>(Oxy + 2 * kp);
    float e0 = ov.x * __expf(-2.0f * xv.x * av.x);
    float e1 = ov.y * __expf(-2.0f * xv.y * av.y);
    float v = pf.x * e0 + pf.y * e1;

    __shared__ float smem[8];
#pragma unroll
    for (int o = 16; o; o >>= 1) v += __shfl_xor_sync(0xffffffffu, v, o);
    if ((kp & 31) == 0) smem[kp >> 5] = v;
    __syncthreads();
    if (kp < 8) {
        float v2 = smem[kp];
#pragma unroll
        for (int o = 4; o; o >>= 1) v2 += __shfl_xor_sync(0x000000ffu, v2, o);
        if (kp == 0) out[b] = v2;
    }
}

// ---------------------------------------------------------------------------
// Launch: 4 kernels, single dependency chain
// ---------------------------------------------------------------------------
extern "C" void kernel_launch(void* const* d_in, const int* in_sizes, int n_in,
                              void* d_out, int out_size) {
    const float* x    = (const float*)d_in[0];   // [64,512]
    const float* W    = (const float*)d_in[1];   // [512,2048]
    const float* bias = (const float*)d_in[2];   // [2048]
    const float* a    = (const float*)d_in[3];   // [512]
    const float* Oxy  = (const float*)d_in[4];   // [512]
    float* out = (float*)d_out;                  // [64]

    z_part_kernel<<<dim3(HDIM / 256, BDIM / 8, NSPLIT), 256>>>(W, x);
    z_comb_kernel<<<256, 256>>>(bias);
    prod_kernel<<<dim3(KP / 32, 1, NCHUNK), 256>>>(W, x);
    reduce_kernel<<<BDIM, 256>>>(x, a, Oxy, out);
}

// round 5
// speedup vs baseline: 6.1193x; 1.0197x over previous
#include <cuda_runtime.h>

// Problem dims (fixed by the dataset)
#define BDIM 64
#define NDIM 512
#define HDIM 2048
#define KP     (NDIM / 2)     // 256 packed k-pairs
#define HC     32             // h-chunk per prod block
#define NCHUNK (HDIM / HC)    // 64 partial-product chunks
#define CG     8              // chunks per reduce1 group
#define NCG    (NCHUNK / CG)  // 8 chunk-groups
#define NSPLIT 8              // n-split for z-GEMM
#define NCK    (NDIM / NSPLIT)

// ---------------------------------------------------------------------------
// Device scratch (allocation-free rule: __device__ globals)
// ---------------------------------------------------------------------------
__device__ float              g_Tt[HDIM * BDIM];                  // [h][b] = tanh(z[b][h])
__device__ unsigned long long g_zp[NSPLIT * HDIM * (BDIM / 2)];   // z partials [ns][h][bp] packed
__device__ unsigned long long g_Ppart[NCHUNK * BDIM * KP];        // [c][b][kp] partial ratio-products
__device__ unsigned long long g_P2[NCG * BDIM * KP];              // [cg][b][kp] stage-1 combined products

// ---------------------------------------------------------------------------
// f32x2 packed helpers
// ---------------------------------------------------------------------------
__device__ __forceinline__ unsigned long long pk2(float lo, float hi) {
    unsigned long long r;
    asm("mov.b64 %0, {%1, %2};" : "=l"(r) : "f"(lo), "f"(hi));
    return r;
}
__device__ __forceinline__ unsigned long long fma2(unsigned long long a, unsigned long long b, unsigned long long c) {
    unsigned long long r;
    asm("fma.rn.f32x2 %0, %1, %2, %3;" : "=l"(r) : "l"(a), "l"(b), "l"(c));
    return r;
}
__device__ __forceinline__ unsigned long long mul2(unsigned long long a, unsigned long long b) {
    unsigned long long r;
    asm("mul.rn.f32x2 %0, %1, %2;" : "=l"(r) : "l"(a), "l"(b));
    return r;
}
__device__ __forceinline__ unsigned long long add2(unsigned long long a, unsigned long long b) {
    unsigned long long r;
    asm("add.rn.f32x2 %0, %1, %2;" : "=l"(r) : "l"(a), "l"(b));
    return r;
}
__device__ __forceinline__ float2 up2(unsigned long long p) {
    float lo, hi;
    asm("mov.b64 {%0, %1}, %2;" : "=f"(lo), "=f"(hi) : "l"(p));
    return make_float2(lo, hi);
}

// ---------------------------------------------------------------------------
// Kernel 1: z partials. Thread = (1 h, 16 b as 8 packed accs), n-chunk NCK.
// grid (HDIM/256, BDIM/16, NSPLIT) = (8, 4, 8) = 256 blocks, block 256.
// W re-read only 4x (16MB total L2 traffic).
// ---------------------------------------------------------------------------
__global__ void __launch_bounds__(256) z_part_kernel(const float* __restrict__ W,
                                                     const float* __restrict__ x) {
    __shared__ float sx[NCK][16];  // [n_local][b_local]
    int t  = threadIdx.x;
    int h  = blockIdx.x * 256 + t;
    int b0 = blockIdx.y * 16;
    int n0 = blockIdx.z * NCK;

    // stage x tile: coalesced reads (lane -> n), conflicted 4KB smem fill (negligible)
#pragma unroll
    for (int j = 0; j < 4; j++) {
        int idx = t + j * 256;               // 0..1023
        int bl = idx >> 6, nl = idx & 63;
        sx[nl][bl] = __ldg(x + (size_t)(b0 + bl) * NDIM + n0 + nl);
    }
    __syncthreads();

    unsigned long long acc[8];
#pragma unroll
    for (int i = 0; i < 8; i++) acc[i] = 0;  // packed +0.0

    const float* wp = W + (size_t)n0 * HDIM + h;
#pragma unroll 4
    for (int n = 0; n < NCK; n++) {
        float w = __ldg(wp + n * HDIM);      // coalesced across threads
        unsigned long long wd = pk2(w, w);
        const ulonglong2* xr = reinterpret_cast<const ulonglong2*>(&sx[n][0]);
        ulonglong2 xA = xr[0];               // b0+0..3  (broadcast)
        ulonglong2 xB = xr[1];               // b0+4..7
        ulonglong2 xC = xr[2];               // b0+8..11
        ulonglong2 xD = xr[3];               // b0+12..15
        acc[0] = fma2(xA.x, wd, acc[0]);
        acc[1] = fma2(xA.y, wd, acc[1]);
        acc[2] = fma2(xB.x, wd, acc[2]);
        acc[3] = fma2(xB.y, wd, acc[3]);
        acc[4] = fma2(xC.x, wd, acc[4]);
        acc[5] = fma2(xC.y, wd, acc[5]);
        acc[6] = fma2(xD.x, wd, acc[6]);
        acc[7] = fma2(xD.y, wd, acc[7]);
    }
    int bp0 = blockIdx.y * 8;
    ulonglong2* zp = reinterpret_cast<ulonglong2*>(
        g_zp + ((size_t)blockIdx.z * HDIM + h) * (BDIM / 2) + bp0);
#pragma unroll
    for (int i = 0; i < 4; i++)
        zp[i] = make_ulonglong2(acc[2 * i], acc[2 * i + 1]);
}

// ---------------------------------------------------------------------------
// Kernel 2: combine z partials + bias, tanh, write Tt[h][b].
// grid 256, block 256 (thread = (h, bp)); 8 independent loads (MLP 8).
// ---------------------------------------------------------------------------
__global__ void __launch_bounds__(256) z_comb_kernel(const float* __restrict__ bias) {
    int idx = blockIdx.x * 256 + threadIdx.x;   // 0..65535
    int h = idx >> 5, bp = idx & 31;
    const unsigned long long* zp = g_zp + (size_t)h * (BDIM / 2) + bp;
    unsigned long long v[NSPLIT];
#pragma unroll
    for (int ns = 0; ns < NSPLIT; ns++)
        v[ns] = __ldg(zp + (size_t)ns * (HDIM * BDIM / 2));
    unsigned long long s = add2(add2(add2(v[0], v[1]), add2(v[2], v[3])),
                                add2(add2(v[4], v[5]), add2(v[6], v[7])));
    float2 z = up2(s);
    float bv = bias[h];
    float2 tv = make_float2(tanhf(z.x + bv), tanhf(z.y + bv));
    *reinterpret_cast<float2*>(g_Tt + (size_t)h * BDIM + 2 * bp) = tv;
}

// ---------------------------------------------------------------------------
// Kernel 3: main product kernel with fused C/S generation.
//   Ppart[c][b][k] = prod_{h in chunk} ( cosh(2W[k,h]) - x[b,k]*tanh(z[b,h])*sinh(2W[k,h]) )
// Thread tile: 1 kp (2 k) x 8 b. grid (KP/32, 1, NCHUNK) = 512 blocks, 3/SM.
// ---------------------------------------------------------------------------
__global__ void __launch_bounds__(256, 3) prod_kernel(const float* __restrict__ W,
                                                      const float* __restrict__ x) {
    __shared__ float sC[HC][66];   // pad 66: conflict-free, LDS.64-aligned
    __shared__ float sS[HC][66];
    int t    = threadIdx.x;
    int lane = t & 31;
    int w    = t >> 5;
    int k0   = blockIdx.x * 64;    // 64 k = 32 kp per block
    int h0   = blockIdx.z * HC;

    // Build C/S tile: coalesced W reads (lane -> h), MUFU expf
#pragma unroll
    for (int j = 0; j < 8; j++) {
        int idx = t + j * 256;                // 0..2047
        int hl = idx & 31, kl = idx >> 5;
        float wv = __ldg(W + (size_t)(k0 + kl) * HDIM + h0 + hl);
        float e  = __expf(2.0f * wv);
        float ei = __expf(-2.0f * wv);
        sC[hl][kl] = 0.5f * (e + ei);
        sS[hl][kl] = 0.5f * (e - ei);
    }

    // -x signs for 8 b at this thread's kp (LDG.64, XOR sign flip)
    int b0 = w * 8;
    unsigned long long nx[8];
#pragma unroll
    for (int i = 0; i < 8; i++) {
        unsigned long long xv = *reinterpret_cast<const unsigned long long*>(
            x + (size_t)(b0 + i) * NDIM + k0 + 2 * lane);
        nx[i] = xv ^ 0x8000000080000000ULL;
    }
    __syncthreads();

    const float4* tp = reinterpret_cast<const float4*>(g_Tt + (size_t)h0 * BDIM + b0);

    unsigned long long acc[8];
#pragma unroll
    for (int i = 0; i < 8; i++) acc[i] = pk2(1.0f, 1.0f);

#pragma unroll 4
    for (int h = 0; h < HC; h++) {
        unsigned long long Cp = *reinterpret_cast<const unsigned long long*>(&sC[h][2 * lane]);
        unsigned long long Sp = *reinterpret_cast<const unsigned long long*>(&sS[h][2 * lane]);
        float4 ta = __ldg(tp + h * (BDIM / 4));       // tanh b0..b0+3 (uniform)
        float4 tb = __ldg(tp + h * (BDIM / 4) + 1);   // tanh b0+4..b0+7
        acc[0] = mul2(acc[0], fma2(mul2(nx[0], pk2(ta.x, ta.x)), Sp, Cp));
        acc[1] = mul2(acc[1], fma2(mul2(nx[1], pk2(ta.y, ta.y)), Sp, Cp));
        acc[2] = mul2(acc[2], fma2(mul2(nx[2], pk2(ta.z, ta.z)), Sp, Cp));
        acc[3] = mul2(acc[3], fma2(mul2(nx[3], pk2(ta.w, ta.w)), Sp, Cp));
        acc[4] = mul2(acc[4], fma2(mul2(nx[4], pk2(tb.x, tb.x)), Sp, Cp));
        acc[5] = mul2(acc[5], fma2(mul2(nx[5], pk2(tb.y, tb.y)), Sp, Cp));
        acc[6] = mul2(acc[6], fma2(mul2(nx[6], pk2(tb.z, tb.z)), Sp, Cp));
        acc[7] = mul2(acc[7], fma2(mul2(nx[7], pk2(tb.w, tb.w)), Sp, Cp));
    }

    int kp = blockIdx.x * 32 + lane;
    unsigned long long* out = g_Ppart + (size_t)blockIdx.z * (BDIM * KP);
#pragma unroll
    for (int i = 0; i < 8; i++)
        out[(size_t)(b0 + i) * KP + kp] = acc[i];
}

// ---------------------------------------------------------------------------
// Kernel 4: reduce stage 1 — combine CG=8 chunks per (b,kp).
// grid (BDIM, NCG) = (64, 8) = 512 blocks, block 256 (thread = kp).
// ---------------------------------------------------------------------------
__global__ void __launch_bounds__(256) reduce1_kernel() {
    int b  = blockIdx.x;
    int cg = blockIdx.y;
    int kp = threadIdx.x;
    const unsigned long long* P =
        g_Ppart + ((size_t)cg * CG) * (BDIM * KP) + (size_t)b * KP + kp;
    unsigned long long v[CG];
#pragma unroll
    for (int i = 0; i < CG; i++)
        v[i] = __ldg(P + (size_t)i * (BDIM * KP));
    unsigned long long p = mul2(mul2(mul2(v[0], v[1]), mul2(v[2], v[3])),
                                mul2(mul2(v[4], v[5]), mul2(v[6], v[7])));
    g_P2[(size_t)cg * (BDIM * KP) + (size_t)b * KP + kp] = p;
}

// ---------------------------------------------------------------------------
// Kernel 5: reduce stage 2 — finish product, apply ea, sum over k.
// grid BDIM, block 256 (thread = kp).
// ---------------------------------------------------------------------------
__global__ void __launch_bounds__(256) reduce2_kernel(const float* __restrict__ x,
                                                      const float* __restrict__ a,
                                                      const float* __restrict__ Oxy,
                                                      float* __restrict__ out) {
    int b  = blockIdx.x;
    int kp = threadIdx.x;
    const unsigned long long* P = g_P2 + (size_t)b * KP + kp;
    unsigned long long v[NCG];
#pragma unroll
    for (int i = 0; i < NCG; i++)
        v[i] = __ldg(P + (size_t)i * (BDIM * KP));
    unsigned long long p = mul2(mul2(mul2(v[0], v[1]), mul2(v[2], v[3])),
                                mul2(mul2(v[4], v[5]), mul2(v[6], v[7])));
    float2 pf = up2(p);
    float2 xv = *reinterpret_cast<const float2*>(x + (size_t)b * NDIM + 2 * kp);
    float2 av = *reinterpret_cast<const float2*>(a + 2 * kp);
    float2 ov = *reinterpret_cast<const float2*>(Oxy + 2 * kp);
    float e0 = ov.x * __expf(-2.0f * xv.x * av.x);
    float e1 = ov.y * __expf(-2.0f * xv.y * av.y);
    float s = pf.x * e0 + pf.y * e1;

    __shared__ float smem[8];
#pragma unroll
    for (int o = 16; o; o >>= 1) s += __shfl_xor_sync(0xffffffffu, s, o);
    if ((kp & 31) == 0) smem[kp >> 5] = s;
    __syncthreads();
    if (kp < 8) {
        float s2 = smem[kp];
#pragma unroll
        for (int o = 4; o; o >>= 1) s2 += __shfl_xor_sync(0x000000ffu, s2, o);
        if (kp == 0) out[b] = s2;
    }
}

// ---------------------------------------------------------------------------
// Launch
// ---------------------------------------------------------------------------
extern "C" void kernel_launch(void* const* d_in, const int* in_sizes, int n_in,
                              void* d_out, int out_size) {
    const float* x    = (const float*)d_in[0];   // [64,512]
    const float* W    = (const float*)d_in[1];   // [512,2048]
    const float* bias = (const float*)d_in[2];   // [2048]
    const float* a    = (const float*)d_in[3];   // [512]
    const float* Oxy  = (const float*)d_in[4];   // [512]
    float* out = (float*)d_out;                  // [64]

    z_part_kernel<<<dim3(HDIM / 256, BDIM / 16, NSPLIT), 256>>>(W, x);
    z_comb_kernel<<<256, 256>>>(bias);
    prod_kernel<<<dim3(KP / 32, 1, NCHUNK), 256>>>(W, x);
    reduce1_kernel<<<dim3(BDIM, NCG), 256>>>();
    reduce2_kernel<<<BDIM, 256>>>(x, a, Oxy, out);
}

// round 7
// speedup vs baseline: 6.5327x; 1.0676x over previous
#include <cuda_runtime.h>

// Problem dims (fixed by the dataset)
#define BDIM 64
#define NDIM 512
#define HDIM 2048
#define KP     (NDIM / 2)     // 256 packed k-pairs
#define HC     64             // h-chunk per prod block
#define NCHUNK (HDIM / HC)    // 32 partial-product chunks
#define NSPLIT 8              // n-split for z-GEMM
#define NCK    (NDIM / NSPLIT)

// ---------------------------------------------------------------------------
// Device scratch (allocation-free rule: __device__ globals)
// ---------------------------------------------------------------------------
__device__ float              g_Tt[HDIM * BDIM];                  // [h][b] = tanh(z[b][h])
__device__ unsigned long long g_zp[NSPLIT * HDIM * (BDIM / 2)];   // z partials [ns][h][bp] packed
__device__ unsigned long long g_Ppart[NCHUNK * BDIM * KP];        // [c][b][kp] partial ratio-products

// ---------------------------------------------------------------------------
// f32x2 packed helpers
// ---------------------------------------------------------------------------
__device__ __forceinline__ unsigned long long pk2(float lo, float hi) {
    unsigned long long r;
    asm("mov.b64 %0, {%1, %2};" : "=l"(r) : "f"(lo), "f"(hi));
    return r;
}
__device__ __forceinline__ unsigned long long fma2(unsigned long long a, unsigned long long b, unsigned long long c) {
    unsigned long long r;
    asm("fma.rn.f32x2 %0, %1, %2, %3;" : "=l"(r) : "l"(a), "l"(b), "l"(c));
    return r;
}
__device__ __forceinline__ unsigned long long mul2(unsigned long long a, unsigned long long b) {
    unsigned long long r;
    asm("mul.rn.f32x2 %0, %1, %2;" : "=l"(r) : "l"(a), "l"(b));
    return r;
}
__device__ __forceinline__ unsigned long long add2(unsigned long long a, unsigned long long b) {
    unsigned long long r;
    asm("add.rn.f32x2 %0, %1, %2;" : "=l"(r) : "l"(a), "l"(b));
    return r;
}
__device__ __forceinline__ float2 up2(unsigned long long p) {
    float lo, hi;
    asm("mov.b64 {%0, %1}, %2;" : "=f"(lo), "=f"(hi) : "l"(p));
    return make_float2(lo, hi);
}

// ---------------------------------------------------------------------------
// Kernel 1: z partials. Thread = (1 h, 16 b as 8 packed accs), n-chunk NCK.
// grid (HDIM/256, BDIM/16, NSPLIT) = (8, 4, 8) = 256 blocks, block 256.
// ---------------------------------------------------------------------------
__global__ void __launch_bounds__(256) z_part_kernel(const float* __restrict__ W,
                                                     const float* __restrict__ x) {
    __shared__ float sx[NCK][16];  // [n_local][b_local]
    int t  = threadIdx.x;
    int h  = blockIdx.x * 256 + t;
    int b0 = blockIdx.y * 16;
    int n0 = blockIdx.z * NCK;

#pragma unroll
    for (int j = 0; j < 4; j++) {
        int idx = t + j * 256;               // 0..1023
        int bl = idx >> 6, nl = idx & 63;
        sx[nl][bl] = __ldg(x + (size_t)(b0 + bl) * NDIM + n0 + nl);
    }
    __syncthreads();

    unsigned long long acc[8];
#pragma unroll
    for (int i = 0; i < 8; i++) acc[i] = 0;  // packed +0.0

    const float* wp = W + (size_t)n0 * HDIM + h;
#pragma unroll 4
    for (int n = 0; n < NCK; n++) {
        float w = __ldg(wp + n * HDIM);      // coalesced across threads
        unsigned long long wd = pk2(w, w);
        const ulonglong2* xr = reinterpret_cast<const ulonglong2*>(&sx[n][0]);
        ulonglong2 xA = xr[0];               // b0+0..3  (broadcast)
        ulonglong2 xB = xr[1];               // b0+4..7
        ulonglong2 xC = xr[2];               // b0+8..11
        ulonglong2 xD = xr[3];               // b0+12..15
        acc[0] = fma2(xA.x, wd, acc[0]);
        acc[1] = fma2(xA.y, wd, acc[1]);
        acc[2] = fma2(xB.x, wd, acc[2]);
        acc[3] = fma2(xB.y, wd, acc[3]);
        acc[4] = fma2(xC.x, wd, acc[4]);
        acc[5] = fma2(xC.y, wd, acc[5]);
        acc[6] = fma2(xD.x, wd, acc[6]);
        acc[7] = fma2(xD.y, wd, acc[7]);
    }
    int bp0 = blockIdx.y * 8;
    ulonglong2* zp = reinterpret_cast<ulonglong2*>(
        g_zp + ((size_t)blockIdx.z * HDIM + h) * (BDIM / 2) + bp0);
#pragma unroll
    for (int i = 0; i < 4; i++)
        zp[i] = make_ulonglong2(acc[2 * i], acc[2 * i + 1]);
}

// ---------------------------------------------------------------------------
// Kernel 2: combine z partials + bias, tanh, write Tt[h][b].
// grid 256, block 256 (thread = (h, bp)); 8 independent loads (MLP 8).
// ---------------------------------------------------------------------------
__global__ void __launch_bounds__(256) z_comb_kernel(const float* __restrict__ bias) {
    int idx = blockIdx.x * 256 + threadIdx.x;   // 0..65535
    int h = idx >> 5, bp = idx & 31;
    const unsigned long long* zp = g_zp + (size_t)h * (BDIM / 2) + bp;
    unsigned long long v[NSPLIT];
#pragma unroll
    for (int ns = 0; ns < NSPLIT; ns++)
        v[ns] = __ldg(zp + (size_t)ns * (HDIM * BDIM / 2));
    unsigned long long s = add2(add2(add2(v[0], v[1]), add2(v[2], v[3])),
                                add2(add2(v[4], v[5]), add2(v[6], v[7])));
    float2 z = up2(s);
    float bv = bias[h];
    float2 tv = make_float2(tanhf(z.x + bv), tanhf(z.y + bv));
    *reinterpret_cast<float2*>(g_Tt + (size_t)h * BDIM + 2 * bp) = tv;
}

// ---------------------------------------------------------------------------
// Kernel 3: main product kernel with fused C/S generation.
//   Ppart[c][b][k] = prod_{h in chunk} ( cosh(2W[k,h]) - x[b,k]*tanh(z[b,h])*sinh(2W[k,h]) )
// Thread tile: 1 kp (2 k) x 8 b over 64 h. grid (KP/32, 1, NCHUNK) = 256
// blocks, block 256, 2 blocks/SM -> single wave on 148 SMs.
// ---------------------------------------------------------------------------
__global__ void __launch_bounds__(256, 2) prod_kernel(const float* __restrict__ W,
                                                      const float* __restrict__ x) {
    __shared__ float sC[HC][66];   // pad 66: conflict-free, LDS.64-aligned
    __shared__ float sS[HC][66];
    int t    = threadIdx.x;
    int lane = t & 31;
    int w    = t >> 5;
    int k0   = blockIdx.x * 64;    // 64 k = 32 kp per block
    int h0   = blockIdx.z * HC;

    // Build C/S tile: coalesced W reads (lanes cover 32 consecutive h), MUFU expf
#pragma unroll
    for (int j = 0; j < 16; j++) {
        int idx = t + j * 256;                // 0..4095 over 64k x 64h
        int hl = idx & 63, kl = idx >> 6;
        float wv = __ldg(W + (size_t)(k0 + kl) * HDIM + h0 + hl);
        float e  = __expf(2.0f * wv);
        float ei = __expf(-2.0f * wv);
        sC[hl][kl] = 0.5f * (e + ei);
        sS[hl][kl] = 0.5f * (e - ei);
    }

    // -x signs for 8 b at this thread's kp (LDG.64, XOR sign flip)
    int b0 = w * 8;
    unsigned long long nx[8];
#pragma unroll
    for (int i = 0; i < 8; i++) {
        unsigned long long xv = *reinterpret_cast<const unsigned long long*>(
            x + (size_t)(b0 + i) * NDIM + k0 + 2 * lane);
        nx[i] = xv ^ 0x8000000080000000ULL;
    }
    __syncthreads();

    const float4* tp = reinterpret_cast<const float4*>(g_Tt + (size_t)h0 * BDIM + b0);

    unsigned long long acc[8];
#pragma unroll
    for (int i = 0; i < 8; i++) acc[i] = pk2(1.0f, 1.0f);

#pragma unroll 4
    for (int h = 0; h < HC; h++) {
        unsigned long long Cp = *reinterpret_cast<const unsigned long long*>(&sC[h][2 * lane]);
        unsigned long long Sp = *reinterpret_cast<const unsigned long long*>(&sS[h][2 * lane]);
        float4 ta = __ldg(tp + h * (BDIM / 4));       // tanh b0..b0+3 (uniform)
        float4 tb = __ldg(tp + h * (BDIM / 4) + 1);   // tanh b0+4..b0+7
        acc[0] = mul2(acc[0], fma2(mul2(nx[0], pk2(ta.x, ta.x)), Sp, Cp));
        acc[1] = mul2(acc[1], fma2(mul2(nx[1], pk2(ta.y, ta.y)), Sp, Cp));
        acc[2] = mul2(acc[2], fma2(mul2(nx[2], pk2(ta.z, ta.z)), Sp, Cp));
        acc[3] = mul2(acc[3], fma2(mul2(nx[3], pk2(ta.w, ta.w)), Sp, Cp));
        acc[4] = mul2(acc[4], fma2(mul2(nx[4], pk2(tb.x, tb.x)), Sp, Cp));
        acc[5] = mul2(acc[5], fma2(mul2(nx[5], pk2(tb.y, tb.y)), Sp, Cp));
        acc[6] = mul2(acc[6], fma2(mul2(nx[6], pk2(tb.z, tb.z)), Sp, Cp));
        acc[7] = mul2(acc[7], fma2(mul2(nx[7], pk2(tb.w, tb.w)), Sp, Cp));
    }

    int kp = blockIdx.x * 32 + lane;
    unsigned long long* out = g_Ppart + (size_t)blockIdx.z * (BDIM * KP);
#pragma unroll
    for (int i = 0; i < 8; i++)
        out[(size_t)(b0 + i) * KP + kp] = acc[i];
}

// ---------------------------------------------------------------------------
// Kernel 4: fused reduce — finish product over all chunks, apply ea, sum.
// grid BDIM, block 256 (thread = kp). 2 waves of 16 independent loads (MLP 16).
// ---------------------------------------------------------------------------
__global__ void __launch_bounds__(256) reduce_kernel(const float* __restrict__ x,
                                                     const float* __restrict__ a,
                                                     const float* __restrict__ Oxy,
                                                     float* __restrict__ out) {
    int b  = blockIdx.x;
    int kp = threadIdx.x;
    const unsigned long long* P = g_Ppart + (size_t)b * KP + kp;

    unsigned long long p = pk2(1.0f, 1.0f);
#pragma unroll
    for (int wv = 0; wv < NCHUNK; wv += 16) {
        unsigned long long v[16];
#pragma unroll
        for (int i = 0; i < 16; i++)
            v[i] = __ldg(P + (size_t)(wv + i) * (BDIM * KP));
        unsigned long long m =
            mul2(mul2(mul2(mul2(v[0], v[1]),  mul2(v[2], v[3])),
                      mul2(mul2(v[4], v[5]),  mul2(v[6], v[7]))),
                 mul2(mul2(mul2(v[8], v[9]),  mul2(v[10], v[11])),
                      mul2(mul2(v[12], v[13]), mul2(v[14], v[15]))));
        p = mul2(p, m);
    }

    float2 pf = up2(p);
    float2 xv = *reinterpret_cast<const float2*>(x + (size_t)b * NDIM + 2 * kp);
    float2 av = *reinterpret_cast<const float2*>(a + 2 * kp);
    float2 ov = *reinterpret_cast<const float2*>(Oxy + 2 * kp);
    float e0 = ov.x * __expf(-2.0f * xv.x * av.x);
    float e1 = ov.y * __expf(-2.0f * xv.y * av.y);
    float s = pf.x * e0 + pf.y * e1;

    __shared__ float smem[8];
#pragma unroll
    for (int o = 16; o; o >>= 1) s += __shfl_xor_sync(0xffffffffu, s, o);
    if ((kp & 31) == 0) smem[kp >> 5] = s;
    __syncthreads();
    if (kp < 8) {
        float s2 = smem[kp];
#pragma unroll
        for (int o = 4; o; o >>= 1) s2 += __shfl_xor_sync(0x000000ffu, s2, o);
        if (kp == 0) out[b] = s2;
    }
}

// ---------------------------------------------------------------------------
// Launch: 4 kernels
// ---------------------------------------------------------------------------
extern "C" void kernel_launch(void* const* d_in, const int* in_sizes, int n_in,
                              void* d_out, int out_size) {
    const float* x    = (const float*)d_in[0];   // [64,512]
    const float* W    = (const float*)d_in[1];   // [512,2048]
    const float* bias = (const float*)d_in[2];   // [2048]
    const float* a    = (const float*)d_in[3];   // [512]
    const float* Oxy  = (const float*)d_in[4];   // [512]
    float* out = (float*)d_out;                  // [64]

    z_part_kernel<<<dim3(HDIM / 256, BDIM / 16, NSPLIT), 256>>>(W, x);
    z_comb_kernel<<<256, 256>>>(bias);
    prod_kernel<<<dim3(KP / 32, 1, NCHUNK), 256>>>(W, x);
    reduce_kernel<<<BDIM, 256>>>(x, a, Oxy, out);
}

// round 9
// speedup vs baseline: 6.9564x; 1.0649x over previous
#include <cuda_runtime.h>

// Problem dims (fixed by the dataset)
#define BDIM 64
#define NDIM 512
#define HDIM 2048
#define KP     (NDIM / 2)     // 256 packed k-pairs
#define HC     64             // h-chunk per prod block
#define NCHUNK (HDIM / HC)    // 32 partial-product chunks
#define NSPLIT 8              // n-split for z-GEMM
#define NCK    (NDIM / NSPLIT)

// ---------------------------------------------------------------------------
// Device scratch (allocation-free rule: __device__ globals)
// ---------------------------------------------------------------------------
__device__ float              g_Tt[HDIM * BDIM];                  // [h][b] = tanh(z[b][h])
__device__ unsigned long long g_zp[NSPLIT * HDIM * (BDIM / 2)];   // z partials [ns][h][bp] packed
__device__ unsigned long long g_Ppart[NCHUNK * BDIM * KP];        // [c][b][kp] partial ratio-products

// ---------------------------------------------------------------------------
// f32x2 packed helpers
// ---------------------------------------------------------------------------
__device__ __forceinline__ unsigned long long pk2(float lo, float hi) {
    unsigned long long r;
    asm("mov.b64 %0, {%1, %2};" : "=l"(r) : "f"(lo), "f"(hi));
    return r;
}
__device__ __forceinline__ unsigned long long fma2(unsigned long long a, unsigned long long b, unsigned long long c) {
    unsigned long long r;
    asm("fma.rn.f32x2 %0, %1, %2, %3;" : "=l"(r) : "l"(a), "l"(b), "l"(c));
    return r;
}
__device__ __forceinline__ unsigned long long mul2(unsigned long long a, unsigned long long b) {
    unsigned long long r;
    asm("mul.rn.f32x2 %0, %1, %2;" : "=l"(r) : "l"(a), "l"(b));
    return r;
}
__device__ __forceinline__ unsigned long long add2(unsigned long long a, unsigned long long b) {
    unsigned long long r;
    asm("add.rn.f32x2 %0, %1, %2;" : "=l"(r) : "l"(a), "l"(b));
    return r;
}
__device__ __forceinline__ float2 up2(unsigned long long p) {
    float lo, hi;
    asm("mov.b64 {%0, %1}, %2;" : "=f"(lo), "=f"(hi) : "l"(p));
    return make_float2(lo, hi);
}

// ---------------------------------------------------------------------------
// Kernel 1: z partials. Thread = (1 h, 16 b as 8 packed accs), n-chunk NCK.
// grid (HDIM/256, BDIM/16, NSPLIT) = (8, 4, 8) = 256 blocks, block 256.
// ---------------------------------------------------------------------------
__global__ void __launch_bounds__(256) z_part_kernel(const float* __restrict__ W,
                                                     const float* __restrict__ x) {
    __shared__ float sx[NCK][16];  // [n_local][b_local]
    int t  = threadIdx.x;
    int h  = blockIdx.x * 256 + t;
    int b0 = blockIdx.y * 16;
    int n0 = blockIdx.z * NCK;

#pragma unroll
    for (int j = 0; j < 4; j++) {
        int idx = t + j * 256;               // 0..1023
        int bl = idx >> 6, nl = idx & 63;
        sx[nl][bl] = __ldg(x + (size_t)(b0 + bl) * NDIM + n0 + nl);
    }
    __syncthreads();

    unsigned long long acc[8];
#pragma unroll
    for (int i = 0; i < 8; i++) acc[i] = 0;  // packed +0.0

    const float* wp = W + (size_t)n0 * HDIM + h;
#pragma unroll 4
    for (int n = 0; n < NCK; n++) {
        float w = __ldg(wp + n * HDIM);      // coalesced across threads
        unsigned long long wd = pk2(w, w);
        const ulonglong2* xr = reinterpret_cast<const ulonglong2*>(&sx[n][0]);
        ulonglong2 xA = xr[0];               // b0+0..3  (broadcast)
        ulonglong2 xB = xr[1];               // b0+4..7
        ulonglong2 xC = xr[2];               // b0+8..11
        ulonglong2 xD = xr[3];               // b0+12..15
        acc[0] = fma2(xA.x, wd, acc[0]);
        acc[1] = fma2(xA.y, wd, acc[1]);
        acc[2] = fma2(xB.x, wd, acc[2]);
        acc[3] = fma2(xB.y, wd, acc[3]);
        acc[4] = fma2(xC.x, wd, acc[4]);
        acc[5] = fma2(xC.y, wd, acc[5]);
        acc[6] = fma2(xD.x, wd, acc[6]);
        acc[7] = fma2(xD.y, wd, acc[7]);
    }
    int bp0 = blockIdx.y * 8;
    ulonglong2* zp = reinterpret_cast<ulonglong2*>(
        g_zp + ((size_t)blockIdx.z * HDIM + h) * (BDIM / 2) + bp0);
#pragma unroll
    for (int i = 0; i < 4; i++)
        zp[i] = make_ulonglong2(acc[2 * i], acc[2 * i + 1]);
}

// ---------------------------------------------------------------------------
// Kernel 2: combine z partials + bias, tanh, write Tt[h][b].
// grid 256, block 256 (thread = (h, bp)); 8 independent loads (MLP 8).
// ---------------------------------------------------------------------------
__global__ void __launch_bounds__(256) z_comb_kernel(const float* __restrict__ bias) {
    int idx = blockIdx.x * 256 + threadIdx.x;   // 0..65535
    int h = idx >> 5, bp = idx & 31;
    const unsigned long long* zp = g_zp + (size_t)h * (BDIM / 2) + bp;
    unsigned long long v[NSPLIT];
#pragma unroll
    for (int ns = 0; ns < NSPLIT; ns++)
        v[ns] = __ldg(zp + (size_t)ns * (HDIM * BDIM / 2));
    unsigned long long s = add2(add2(add2(v[0], v[1]), add2(v[2], v[3])),
                                add2(add2(v[4], v[5]), add2(v[6], v[7])));
    float2 z = up2(s);
    float bv = bias[h];
    float2 tv = make_float2(tanhf(z.x + bv), tanhf(z.y + bv));
    *reinterpret_cast<float2*>(g_Tt + (size_t)h * BDIM + 2 * bp) = tv;
}

// ---------------------------------------------------------------------------
// Kernel 3: main product kernel with fused C/S generation.
//   Ppart[c][b][k] = prod_{h in chunk} ( cosh(2W[k,h]) - x[b,k]*tanh(z[b,h])*sinh(2W[k,h]) )
// Thread tile: 1 kp (2 k) x 8 b over 64 h. grid (KP/32, 1, NCHUNK) = 256
// blocks, block 256, 2 blocks/SM -> single wave on 148 SMs.
// ---------------------------------------------------------------------------
__global__ void __launch_bounds__(256, 2) prod_kernel(const float* __restrict__ W,
                                                      const float* __restrict__ x) {
    __shared__ float sC[HC][66];   // pad 66: conflict-free, LDS.64-aligned
    __shared__ float sS[HC][66];
    int t    = threadIdx.x;
    int lane = t & 31;
    int w    = t >> 5;
    int k0   = blockIdx.x * 64;    // 64 k = 32 kp per block
    int h0   = blockIdx.z * HC;

    // Build C/S tile: coalesced W reads (lanes cover consecutive h), MUFU expf
#pragma unroll
    for (int j = 0; j < 16; j++) {
        int idx = t + j * 256;                // 0..4095 over 64k x 64h
        int hl = idx & 63, kl = idx >> 6;
        float wv = __ldg(W + (size_t)(k0 + kl) * HDIM + h0 + hl);
        float e  = __expf(2.0f * wv);
        float ei = __expf(-2.0f * wv);
        sC[hl][kl] = 0.5f * (e + ei);
        sS[hl][kl] = 0.5f * (e - ei);
    }

    // -x signs for 8 b at this thread's kp (LDG.64, XOR sign flip)
    int b0 = w * 8;
    unsigned long long nx[8];
#pragma unroll
    for (int i = 0; i < 8; i++) {
        unsigned long long xv = *reinterpret_cast<const unsigned long long*>(
            x + (size_t)(b0 + i) * NDIM + k0 + 2 * lane);
        nx[i] = xv ^ 0x8000000080000000ULL;
    }
    __syncthreads();

    const float4* tp = reinterpret_cast<const float4*>(g_Tt + (size_t)h0 * BDIM + b0);

    unsigned long long acc[8];
#pragma unroll
    for (int i = 0; i < 8; i++) acc[i] = pk2(1.0f, 1.0f);

#pragma unroll 4
    for (int h = 0; h < HC; h++) {
        unsigned long long Cp = *reinterpret_cast<const unsigned long long*>(&sC[h][2 * lane]);
        unsigned long long Sp = *reinterpret_cast<const unsigned long long*>(&sS[h][2 * lane]);
        float4 ta = __ldg(tp + h * (BDIM / 4));       // tanh b0..b0+3 (uniform)
        float4 tb = __ldg(tp + h * (BDIM / 4) + 1);   // tanh b0+4..b0+7
        acc[0] = mul2(acc[0], fma2(mul2(nx[0], pk2(ta.x, ta.x)), Sp, Cp));
        acc[1] = mul2(acc[1], fma2(mul2(nx[1], pk2(ta.y, ta.y)), Sp, Cp));
        acc[2] = mul2(acc[2], fma2(mul2(nx[2], pk2(ta.z, ta.z)), Sp, Cp));
        acc[3] = mul2(acc[3], fma2(mul2(nx[3], pk2(ta.w, ta.w)), Sp, Cp));
        acc[4] = mul2(acc[4], fma2(mul2(nx[4], pk2(tb.x, tb.x)), Sp, Cp));
        acc[5] = mul2(acc[5], fma2(mul2(nx[5], pk2(tb.y, tb.y)), Sp, Cp));
        acc[6] = mul2(acc[6], fma2(mul2(nx[6], pk2(tb.z, tb.z)), Sp, Cp));
        acc[7] = mul2(acc[7], fma2(mul2(nx[7], pk2(tb.w, tb.w)), Sp, Cp));
    }

    int kp = blockIdx.x * 32 + lane;
    unsigned long long* out = g_Ppart + (size_t)blockIdx.z * (BDIM * KP);
#pragma unroll
    for (int i = 0; i < 8; i++)
        out[(size_t)(b0 + i) * KP + kp] = acc[i];
}

// ---------------------------------------------------------------------------
// Kernel 4: fused reduce, chunk-product parallelized across threads.
// grid BDIM, block 1024: thread = (kp, cg), cg in 0..3, each multiplies 8
// independent chunk values (true MLP-8), partials combined via smem; first
// 256 threads apply ea = Oxy*exp(-2*x*a) and tree-sum over k.
// ---------------------------------------------------------------------------
__global__ void __launch_bounds__(1024) reduce_kernel(const float* __restrict__ x,
                                                      const float* __restrict__ a,
                                                      const float* __restrict__ Oxy,
                                                      float* __restrict__ out) {
    __shared__ unsigned long long sp[1024];
    __shared__ float ssum[8];
    int b  = blockIdx.x;
    int t  = threadIdx.x;
    int kp = t & 255;
    int cg = t >> 8;            // 0..3 -> chunks cg*8 .. cg*8+7

    const unsigned long long* P =
        g_Ppart + (size_t)(cg * 8) * (BDIM * KP) + (size_t)b * KP + kp;
    unsigned long long v[8];
#pragma unroll
    for (int i = 0; i < 8; i++)
        v[i] = __ldg(P + (size_t)i * (BDIM * KP));
    sp[t] = mul2(mul2(mul2(v[0], v[1]), mul2(v[2], v[3])),
                 mul2(mul2(v[4], v[5]), mul2(v[6], v[7])));
    __syncthreads();

    if (t < 256) {
        unsigned long long p = mul2(mul2(sp[t], sp[t + 256]),
                                    mul2(sp[t + 512], sp[t + 768]));
        float2 pf = up2(p);
        float2 xv = *reinterpret_cast<const float2*>(x + (size_t)b * NDIM + 2 * kp);
        float2 av = *reinterpret_cast<const float2*>(a + 2 * kp);
        float2 ov = *reinterpret_cast<const float2*>(Oxy + 2 * kp);
        float e0 = ov.x * __expf(-2.0f * xv.x * av.x);
        float e1 = ov.y * __expf(-2.0f * xv.y * av.y);
        float s = pf.x * e0 + pf.y * e1;

#pragma unroll
        for (int o = 16; o; o >>= 1) s += __shfl_xor_sync(0xffffffffu, s, o);
        if ((t & 31) == 0) ssum[t >> 5] = s;
    }
    __syncthreads();
    if (t < 8) {
        float s2 = ssum[t];
#pragma unroll
        for (int o = 4; o; o >>= 1) s2 += __shfl_xor_sync(0x000000ffu, s2, o);
        if (t == 0) out[b] = s2;
    }
}

// ---------------------------------------------------------------------------
// Launch: 4 kernels
// ---------------------------------------------------------------------------
extern "C" void kernel_launch(void* const* d_in, const int* in_sizes, int n_in,
                              void* d_out, int out_size) {
    const float* x    = (const float*)d_in[0];   // [64,512]
    const float* W    = (const float*)d_in[1];   // [512,2048]
    const float* bias = (const float*)d_in[2];   // [2048]
    const float* a    = (const float*)d_in[3];   // [512]
    const float* Oxy  = (const float*)d_in[4];   // [512]
    float* out = (float*)d_out;                  // [64]

    z_part_kernel<<<dim3(HDIM / 256, BDIM / 16, NSPLIT), 256>>>(W, x);
    z_comb_kernel<<<256, 256>>>(bias);
    prod_kernel<<<dim3(KP / 32, 1, NCHUNK), 256>>>(W, x);
    reduce_kernel<<<BDIM, 1024>>>(x, a, Oxy, out);
}